// round 12
// baseline (speedup 1.0000x reference)
#include <cuda_runtime.h>
#include <stdint.h>
#include <math.h>

#define NND 2048
#define NE  65536
#define H1  32
#define H2  20
#define NNSQ (NND*NND)
#define GRID 132
#define TPB  1024

// -------- persistent scratch (device globals; no runtime allocation) --------
// State machine across graph replays: d_degc, d_xcum, g_cnt return to zero by
// the end of each full call (d_h1 zeroed in prologue phase F, d_degc/d_xcum in
// k_tail). Module load provides the initial zeros.
__device__ int   d_degc[NND];                   // in-degree counts (zeroed by k_tail)
__device__ __align__(16) float d_h1[NND*H1];    // zeroed by phase F for next call
__device__ __align__(16) float d_h2[NND*H2];
__device__ int   d_rowoff[NND];
__device__ int   d_cursor[NND];
__device__ int   d_srcs[NE];
__device__ float d_xcum[H2];                    // zeroed by k_tail
__device__ float    d_rowval[NND];
__device__ unsigned d_rowidx[NND];
__device__ float    d_rowm[NND];
__device__ float    d_rowz[NND];
__device__ volatile unsigned g_cnt;             // barrier arrivals (returns to 0)
__device__ volatile unsigned g_gen;             // barrier generation (monotonic)

// dual-dtype edge index accessor (pos in [0, 2*NE))
__device__ __forceinline__ int load_ei(const void* ei, int pos, int is64) {
    if (is64) return (int)((const long long*)ei)[pos];
    return ((const int*)ei)[pos];
}

__device__ __forceinline__ int detect64(const void* ei) {
    const long long* p = (const long long*)ei;
    int is64 = 1;
    #pragma unroll
    for (int k = 0; k < 16; k++) {
        long long v = p[k];
        if (v < 0 || v >= NND) is64 = 0;
    }
    return is64;
}

// grid-wide barrier; safe because grid (132) <= SM count -> all blocks resident.
__device__ __forceinline__ void grid_bar() {
    __syncthreads();
    if (threadIdx.x == 0) {
        unsigned gen = g_gen;
        __threadfence();                         // release prior writes
        if (atomicAdd((unsigned*)&g_cnt, 1u) == GRID - 1u) {
            g_cnt = 0u;
            __threadfence();
            g_gen = gen + 1u;
        } else {
            while (g_gen == gen) __nanosleep(64);
        }
        __threadfence();                         // acquire
    }
    __syncthreads();
}

// pair combine: max value, tie -> smaller index (first occurrence)
__device__ __forceinline__ void pair_take(float& v, unsigned& i, float v2, unsigned i2) {
    if (v2 > v || (v2 == v && i2 < i)) { v = v2; i = i2; }
}

__device__ __forceinline__ void warp_pair_reduce(float& v, unsigned& i) {
    #pragma unroll
    for (int o = 16; o; o >>= 1) {
        float    v2 = __shfl_xor_sync(0xffffffffu, v, o);
        unsigned i2 = __shfl_xor_sync(0xffffffffu, i, o);
        pair_take(v, i, v2, i2);
    }
}

__device__ __forceinline__ void block_pair_reduce(float& v, unsigned& i,
                                                  float* sval, unsigned* sidx) {
    warp_pair_reduce(v, i);
    int lane = threadIdx.x & 31, wid = threadIdx.x >> 5;
    if (lane == 0) { sval[wid] = v; sidx[wid] = i; }
    __syncthreads();
    if (wid == 0) {
        int nw = (blockDim.x + 31) >> 5;
        if (lane < nw) { v = sval[lane]; i = sidx[lane]; }
        else           { v = -3.402823e38f; i = 0xFFFFFFFFu; }
        warp_pair_reduce(v, i);
        if (lane == 0) { sval[0] = v; sidx[0] = i; }
    }
    __syncthreads();
    v = sval[0]; i = sidx[0];
    __syncthreads();
}

__device__ __forceinline__ float block_reduce_max(float v, float* red) {
    __syncthreads();
    int lane = threadIdx.x & 31, wid = threadIdx.x >> 5;
    #pragma unroll
    for (int o = 16; o; o >>= 1) v = fmaxf(v, __shfl_xor_sync(0xffffffffu, v, o));
    if (lane == 0) red[wid] = v;
    __syncthreads();
    if (wid == 0) {
        int nw = (blockDim.x + 31) >> 5;
        v = (lane < nw) ? red[lane] : -3.402823e38f;
        #pragma unroll
        for (int o = 16; o; o >>= 1) v = fmaxf(v, __shfl_xor_sync(0xffffffffu, v, o));
        if (lane == 0) red[0] = v;
    }
    __syncthreads();
    return red[0];
}

__device__ __forceinline__ float block_reduce_sum(float v, float* red) {
    __syncthreads();
    int lane = threadIdx.x & 31, wid = threadIdx.x >> 5;
    #pragma unroll
    for (int o = 16; o; o >>= 1) v += __shfl_xor_sync(0xffffffffu, v, o);
    if (lane == 0) red[wid] = v;
    __syncthreads();
    if (wid == 0) {
        int nw = (blockDim.x + 31) >> 5;
        v = (lane < nw) ? red[lane] : 0.f;
        #pragma unroll
        for (int o = 16; o; o >>= 1) v += __shfl_xor_sync(0xffffffffu, v, o);
        if (lane == 0) red[0] = v;
    }
    __syncthreads();
    return red[0];
}

// ======== persistent prologue: deg+gemm1 | scan | scatter | agg1+gemm2 | agg2+colmean
__global__ void __launch_bounds__(TPB, 1) k_pro(const float* __restrict__ X,
                                                const float* __restrict__ W1,
                                                const void* __restrict__ ei,
                                                const float* __restrict__ W2,
                                                const float* __restrict__ b1,
                                                const float* __restrict__ b2) {
    __shared__ float Xs[64][64];
    __shared__ float Ws[64][H1];
    __shared__ float W2s[H1][H2];
    __shared__ float colsum[32][H2];
    __shared__ int   wsum[32];
    int t = threadIdx.x;
    int gw0 = blockIdx.x * TPB + t;
    int lane = t & 31, wid = t >> 5;

    // ---- phase B: degree count (all blocks) + gemm1 (blocks 0..127) ----
    {
        int is64 = detect64(ei);
        for (int e = gw0; e < NE; e += GRID * TPB) {
            int s = load_ei(ei, e, is64);
            int d = load_ei(ei, NE + e, is64);
            if ((unsigned)s < NND && (unsigned)d < NND) atomicAdd(&d_degc[d], 1);
        }
    }
    if (blockIdx.x < 128) {
        int rb = blockIdx.x >> 2;          // 0..31 row block
        int ks = blockIdx.x & 3;           // 0..3 k split
        int row0 = rb * 64;
        int col = lane;                    // output col 0..31
        int rg = wid;                      // row group 0..31 -> rows rg*2, rg*2+1
        float acc0 = 0.f, acc1 = 0.f;
        #pragma unroll 1
        for (int c8 = 0; c8 < 8; c8++) {
            int k0 = ks * 512 + c8 * 64;
            {
                int r = t >> 4, c = t & 15;
                float4 v = __ldg((const float4*)&X[(size_t)(row0 + r)*NND + k0 + c*4]);
                Xs[r][4*c + 0] = v.x; Xs[r][4*c + 1] = v.y;
                Xs[r][4*c + 2] = v.z; Xs[r][4*c + 3] = v.w;
            }
            if (t < 512) {
                int r = t >> 3, c = t & 7;
                float4 v = __ldg((const float4*)&W1[(size_t)(k0 + r)*H1 + 4*c]);
                Ws[r][4*c + 0] = v.x; Ws[r][4*c + 1] = v.y;
                Ws[r][4*c + 2] = v.z; Ws[r][4*c + 3] = v.w;
            }
            __syncthreads();
            #pragma unroll 16
            for (int kk = 0; kk < 64; kk++) {
                float wv = Ws[kk][col];
                acc0 = fmaf(Xs[rg*2][kk],     wv, acc0);
                acc1 = fmaf(Xs[rg*2 + 1][kk], wv, acc1);
            }
            __syncthreads();
        }
        atomicAdd(&d_h1[(size_t)(row0 + rg*2)*H1 + col],     acc0);
        atomicAdd(&d_h1[(size_t)(row0 + rg*2 + 1)*H1 + col], acc1);
    }
    grid_bar();

    // ---- phase C: exclusive scan of in-degrees (block 0) ----
    if (blockIdx.x == 0) {
        int c0 = __ldcg(&d_degc[2*t]);
        int c1 = __ldcg(&d_degc[2*t + 1]);
        int p = c0 + c1;
        int v = p;
        #pragma unroll
        for (int o = 1; o < 32; o <<= 1) {
            int u = __shfl_up_sync(0xffffffffu, v, o);
            if (lane >= o) v += u;
        }
        if (lane == 31) wsum[wid] = v;
        __syncthreads();
        if (wid == 0) {
            int w = wsum[lane];
            #pragma unroll
            for (int o = 1; o < 32; o <<= 1) {
                int u = __shfl_up_sync(0xffffffffu, w, o);
                if (lane >= o) w += u;
            }
            wsum[lane] = w;
        }
        __syncthreads();
        int base = (wid > 0) ? wsum[wid - 1] : 0;
        int excl = base + v - p;
        d_rowoff[2*t]     = excl;
        d_rowoff[2*t + 1] = excl + c0;
        d_cursor[2*t]     = excl;
        d_cursor[2*t + 1] = excl + c0;
    }
    grid_bar();

    // ---- phase D: scatter sources into CSR order ----
    {
        int is64 = detect64(ei);
        for (int e = gw0; e < NE; e += GRID * TPB) {
            int s = load_ei(ei, e, is64);
            int d = load_ei(ei, NE + e, is64);
            if ((unsigned)s < NND && (unsigned)d < NND) {
                int pos = atomicAdd(&d_cursor[d], 1);
                d_srcs[pos] = s;
            }
        }
    }
    grid_bar();

    // ---- phase E: gather-agg1 + relu + gemm2 (warp per node) ----
    for (int i = t; i < H1*H2; i += TPB) W2s[i / H2][i % H2] = W2[i];
    __syncthreads();
    {
        int n = blockIdx.x * 32 + wid;
        if (n < NND) {
            int dc = __ldcg(&d_degc[n]);
            float dinvd = rsqrtf((float)(dc + 1));
            int start = __ldcg(&d_rowoff[n]);
            int end = start + dc;
            float acc = 0.f;
            int i = start;
            for (; i + 4 <= end; i += 4) {
                int s0 = __ldcg(&d_srcs[i]),   s1 = __ldcg(&d_srcs[i+1]);
                int s2 = __ldcg(&d_srcs[i+2]), s3 = __ldcg(&d_srcs[i+3]);
                float n0 = rsqrtf((float)(__ldcg(&d_degc[s0]) + 1));
                float n1 = rsqrtf((float)(__ldcg(&d_degc[s1]) + 1));
                float n2 = rsqrtf((float)(__ldcg(&d_degc[s2]) + 1));
                float n3 = rsqrtf((float)(__ldcg(&d_degc[s3]) + 1));
                acc = fmaf(__ldcg(&d_h1[s0*H1 + lane]), n0, acc);
                acc = fmaf(__ldcg(&d_h1[s1*H1 + lane]), n1, acc);
                acc = fmaf(__ldcg(&d_h1[s2*H1 + lane]), n2, acc);
                acc = fmaf(__ldcg(&d_h1[s3*H1 + lane]), n3, acc);
            }
            for (; i < end; i++) {
                int s0 = __ldcg(&d_srcs[i]);
                float n0 = rsqrtf((float)(__ldcg(&d_degc[s0]) + 1));
                acc = fmaf(__ldcg(&d_h1[s0*H1 + lane]), n0, acc);
            }
            float self = __ldcg(&d_h1[n*H1 + lane]) * dinvd * dinvd;
            float o1 = fmaxf(acc * dinvd + self + __ldg(&b1[lane]), 0.f);
            float s = 0.f;
            #pragma unroll
            for (int k = 0; k < H1; k++) {
                float ok = __shfl_sync(0xffffffffu, o1, k);
                if (lane < H2) s = fmaf(ok, W2s[k][lane], s);
            }
            if (lane < H2) d_h2[n*H2 + lane] = s;
        }
    }
    grid_bar();

    // ---- phase F: gather-agg2 + relu + column-mean partials; zero h1 for next call ----
    {
        int n = blockIdx.x * 32 + wid;
        float o2 = 0.f;
        if (n < NND) {
            int dc = __ldcg(&d_degc[n]);
            float dinvd = rsqrtf((float)(dc + 1));
            int start = __ldcg(&d_rowoff[n]);
            int end = start + dc;
            float acc = 0.f;
            int i = start;
            for (; i + 4 <= end; i += 4) {
                int s0 = __ldcg(&d_srcs[i]),   s1 = __ldcg(&d_srcs[i+1]);
                int s2 = __ldcg(&d_srcs[i+2]), s3 = __ldcg(&d_srcs[i+3]);
                float n0 = rsqrtf((float)(__ldcg(&d_degc[s0]) + 1));
                float n1 = rsqrtf((float)(__ldcg(&d_degc[s1]) + 1));
                float n2 = rsqrtf((float)(__ldcg(&d_degc[s2]) + 1));
                float n3 = rsqrtf((float)(__ldcg(&d_degc[s3]) + 1));
                if (lane < H2) {
                    acc = fmaf(__ldcg(&d_h2[s0*H2 + lane]), n0, acc);
                    acc = fmaf(__ldcg(&d_h2[s1*H2 + lane]), n1, acc);
                    acc = fmaf(__ldcg(&d_h2[s2*H2 + lane]), n2, acc);
                    acc = fmaf(__ldcg(&d_h2[s3*H2 + lane]), n3, acc);
                }
            }
            for (; i < end; i++) {
                int s0 = __ldcg(&d_srcs[i]);
                float n0 = rsqrtf((float)(__ldcg(&d_degc[s0]) + 1));
                if (lane < H2) acc = fmaf(__ldcg(&d_h2[s0*H2 + lane]), n0, acc);
            }
            if (lane < H2) {
                float self = __ldcg(&d_h2[n*H2 + lane]) * dinvd * dinvd;
                o2 = fmaxf(acc * dinvd + self + __ldg(&b2[lane]), 0.f);
            }
        }
        if (lane < H2) colsum[wid][lane] = o2;
        __syncthreads();
        if (t < H2) {
            float s = 0.f;
            #pragma unroll
            for (int r = 0; r < 32; r++) s += colsum[r][t];
            atomicAdd(&d_xcum[t], s);
        }
        // zero h1 for next graph replay (h1 fully consumed in phase E)
        for (int i = gw0; i < NND*H1; i += GRID * TPB) d_h1[i] = 0.f;
    }
}

// Fused: logits row -> softmax stats -> per-row argmax (no probs store)
__global__ void __launch_bounds__(512) k_logits(const float* __restrict__ aW,
                                                const float* __restrict__ ab) {
    __shared__ float xa[H2];
    __shared__ float red[32];
    __shared__ float    sval[16];
    __shared__ unsigned sidx[16];
    int t = threadIdx.x;
    int row = blockIdx.x;
    if (t < H2) xa[t] = d_xcum[t] * (1.f / NND);
    __syncthreads();
    size_t base = (size_t)row * NND;
    float l[4];
    {
        float4 a0 = __ldcs((const float4*)&ab[base + 4*t]);
        l[0]=a0.x; l[1]=a0.y; l[2]=a0.z; l[3]=a0.w;
    }
    #pragma unroll
    for (int k = 0; k < H2; k++) {
        float xv = xa[k];
        float4 v0 = __ldcs((const float4*)&aW[(size_t)k * NNSQ + base + 4*t]);
        l[0] = fmaf(xv, v0.x, l[0]); l[1] = fmaf(xv, v0.y, l[1]);
        l[2] = fmaf(xv, v0.z, l[2]); l[3] = fmaf(xv, v0.w, l[3]);
    }
    float m = fmaxf(fmaxf(l[0], l[1]), fmaxf(l[2], l[3]));
    m = block_reduce_max(m, red);
    float e[4]; float s = 0.f;
    #pragma unroll
    for (int c = 0; c < 4; c++) { e[c] = expf(l[c] - m); s += e[c]; }
    s = block_reduce_sum(s, red);
    float p[4];
    #pragma unroll
    for (int c = 0; c < 4; c++) p[c] = e[c] / s;
    float bv = p[0]; unsigned bc = (unsigned)(4*t);
    #pragma unroll
    for (int c = 1; c < 4; c++)
        if (p[c] > bv) { bv = p[c]; bc = (unsigned)(4*t + c); }
    unsigned gi = (unsigned)base + bc;
    warp_pair_reduce(bv, gi);
    int lane = t & 31, wid = t >> 5;
    if (lane == 0) { sval[wid] = bv; sidx[wid] = gi; }
    __syncthreads();
    if (t == 0) {
        float v = sval[0]; unsigned i = sidx[0];
        #pragma unroll
        for (int w = 1; w < 16; w++) pair_take(v, i, sval[w], sidx[w]);
        d_rowval[row] = v; d_rowidx[row] = i;
        d_rowm[row] = m; d_rowz[row] = s;
    }
}

// Single-block tail: argmaxes -> output; also resets degc/xcum for next call.
__global__ void __launch_bounds__(256) k_tail(const float* __restrict__ aW,
                                              const float* __restrict__ ab,
                                              const float* __restrict__ cW,
                                              const float* __restrict__ cb,
                                              float* __restrict__ out, int out_size) {
    __shared__ float    sval[8];
    __shared__ unsigned sidx[8];
    __shared__ float xa[H2];
    int t = threadIdx.x;
    if (t < H2) xa[t] = d_xcum[t] * (1.f / NND);
    __syncthreads();

    float v = -1.f; unsigned i = 0xFFFFFFFFu;
    for (int r = t; r < NND; r += 256) pair_take(v, i, d_rowval[r], d_rowidx[r]);
    block_pair_reduce(v, i, sval, sidx);
    unsigned idx1 = i;
    unsigned r1 = idx1 >> 11, c1 = idx1 & 2047u;

    float v2 = -1.f; unsigned i2 = 0xFFFFFFFFu;
    for (unsigned r = t; r < r1; r += 256) pair_take(v2, i2, d_rowval[r], d_rowidx[r]);
    if (c1 > 0) {
        float m1 = d_rowm[r1], z1 = d_rowz[r1];
        size_t base = (size_t)r1 * NND;
        for (unsigned c = t; c < c1; c += 256) {
            float l = __ldg(&ab[base + c]);
            #pragma unroll
            for (int k = 0; k < H2; k++)
                l = fmaf(xa[k], __ldg(&aW[(size_t)k * NNSQ + base + c]), l);
            float p = expf(l - m1) / z1;
            pair_take(v2, i2, p, (unsigned)base + c);
        }
    }
    block_pair_reduce(v2, i2, sval, sidx);
    unsigned idx2 = (v2 >= 0.f) ? i2 : 0u;

    if (t == 0) {
        unsigned a0 = idx1 >> 11, a1 = idx1 & 2047u;
        unsigned a2 = idx2 >> 11, a3 = idx2 & 2047u;
        float m0 = d_rowm[0], z0 = d_rowz[0];
        unsigned ai[4] = {a0, a1, a2, a3};
        float lp[4];
        #pragma unroll
        for (int q = 0; q < 4; q++) {
            unsigned j = ai[q];
            float l = ab[j];
            #pragma unroll
            for (int k = 0; k < H2; k++)
                l = fmaf(xa[k], aW[(size_t)k * NNSQ + j], l);
            float p = expf(l - m0) / z0;
            lp[q] = -logf(p);
        }
        float critic = cb[0];
        #pragma unroll
        for (int k = 0; k < H2; k++) critic = fmaf(xa[k], cW[k], critic);
        float o[9];
        o[0] = (float)a0; o[1] = (float)a1; o[2] = (float)a2; o[3] = (float)a3;
        o[4] = lp[0]; o[5] = lp[1]; o[6] = lp[2]; o[7] = lp[3];
        o[8] = critic;
        int n = out_size < 9 ? out_size : 9;
        for (int q = 0; q < n; q++) out[q] = o[q];
    }
    // cleanup for next graph replay (all consumers of degc/xcum are done)
    for (int i = t; i < NND; i += 256) d_degc[i] = 0;
    if (t < H2) d_xcum[t] = 0.f;
}

extern "C" void kernel_launch(void* const* d_in, const int* in_sizes, int n_in,
                              void* d_out, int out_size) {
    const float* x   = (const float*)d_in[0];
    const void*  ei  = d_in[1];
    const float* W1  = (const float*)d_in[2];
    const float* b1  = (const float*)d_in[3];
    const float* W2  = (const float*)d_in[4];
    const float* b2  = (const float*)d_in[5];
    const float* aW  = (const float*)d_in[6];
    const float* ab  = (const float*)d_in[7];
    const float* cW  = (const float*)d_in[8];
    const float* cb  = (const float*)d_in[9];
    float* out = (float*)d_out;

    k_pro    <<<GRID, TPB>>>(x, W1, ei, W2, b1, b2);
    k_logits <<<2048, 512>>>(aW, ab);
    k_tail   <<<1,    256>>>(aW, ab, cW, cb, out, out_size);
}

// round 13
// speedup vs baseline: 1.0161x; 1.0161x over previous
#include <cuda_runtime.h>
#include <stdint.h>
#include <math.h>

#define NND 2048
#define NE  65536
#define H1  32
#define H2  20
#define NNSQ (NND*NND)

// -------- zeroed scratch (single cudaMemsetAsync per call) --------
#define SC_DEGC  0                       // int counts [NND]
#define SC_H1    (SC_DEGC + NND)
#define SC_AGG1  (SC_H1 + NND*H1)
#define SC_AGG2  (SC_AGG1 + NND*H1)
#define SC_TICK  (SC_AGG2 + NND*H2)
#define SC_TOTAL (SC_TICK + 4)
__device__ __align__(16) float d_scratch[SC_TOTAL];
#define d_degc  ((int*)(d_scratch + SC_DEGC))
#define d_h1    (d_scratch + SC_H1)
#define d_agg1  (d_scratch + SC_AGG1)
#define d_agg2  (d_scratch + SC_AGG2)
#define d_tick  ((unsigned*)(d_scratch + SC_TICK))

__device__ __align__(16) float d_h2[NND*H2];
__device__ float d_xactor[H2];
__device__ float    d_rowval[NND];
__device__ unsigned d_rowidx[NND];
__device__ float    d_rowm[NND];
__device__ float    d_rowz[NND];
__device__ int      d_ei64;   // published by k_gemm1 block (0,0)

// dual-dtype edge index accessor (pos in [0, 2*NE))
__device__ __forceinline__ int load_ei(const void* ei, int pos, int is64) {
    if (is64) return (int)((const long long*)ei)[pos];
    return ((const int*)ei)[pos];
}

__device__ __forceinline__ int detect64(const void* ei) {
    const long long* p = (const long long*)ei;
    int is64 = 1;
    #pragma unroll
    for (int k = 0; k < 16; k++) {
        long long v = p[k];
        if (v < 0 || v >= NND) is64 = 0;
    }
    return is64;
}

// pair combine: max value, tie -> smaller index (first occurrence)
__device__ __forceinline__ void pair_take(float& v, unsigned& i, float v2, unsigned i2) {
    if (v2 > v || (v2 == v && i2 < i)) { v = v2; i = i2; }
}

__device__ __forceinline__ void warp_pair_reduce(float& v, unsigned& i) {
    #pragma unroll
    for (int o = 16; o; o >>= 1) {
        float    v2 = __shfl_xor_sync(0xffffffffu, v, o);
        unsigned i2 = __shfl_xor_sync(0xffffffffu, i, o);
        pair_take(v, i, v2, i2);
    }
}

__device__ __forceinline__ void block_pair_reduce(float& v, unsigned& i,
                                                  float* sval, unsigned* sidx) {
    warp_pair_reduce(v, i);
    int lane = threadIdx.x & 31, wid = threadIdx.x >> 5;
    if (lane == 0) { sval[wid] = v; sidx[wid] = i; }
    __syncthreads();
    if (wid == 0) {
        int nw = (blockDim.x + 31) >> 5;
        if (lane < nw) { v = sval[lane]; i = sidx[lane]; }
        else           { v = -3.402823e38f; i = 0xFFFFFFFFu; }
        warp_pair_reduce(v, i);
        if (lane == 0) { sval[0] = v; sidx[0] = i; }
    }
    __syncthreads();
    v = sval[0]; i = sidx[0];
    __syncthreads();
}

__device__ __forceinline__ float block_reduce_max(float v, float* red) {
    __syncthreads();
    int lane = threadIdx.x & 31, wid = threadIdx.x >> 5;
    #pragma unroll
    for (int o = 16; o; o >>= 1) v = fmaxf(v, __shfl_xor_sync(0xffffffffu, v, o));
    if (lane == 0) red[wid] = v;
    __syncthreads();
    if (wid == 0) {
        int nw = (blockDim.x + 31) >> 5;
        v = (lane < nw) ? red[lane] : -3.402823e38f;
        #pragma unroll
        for (int o = 16; o; o >>= 1) v = fmaxf(v, __shfl_xor_sync(0xffffffffu, v, o));
        if (lane == 0) red[0] = v;
    }
    __syncthreads();
    return red[0];
}

__device__ __forceinline__ float block_reduce_sum(float v, float* red) {
    __syncthreads();
    int lane = threadIdx.x & 31, wid = threadIdx.x >> 5;
    #pragma unroll
    for (int o = 16; o; o >>= 1) v += __shfl_xor_sync(0xffffffffu, v, o);
    if (lane == 0) red[wid] = v;
    __syncthreads();
    if (wid == 0) {
        int nw = (blockDim.x + 31) >> 5;
        v = (lane < nw) ? red[lane] : 0.f;
        #pragma unroll
        for (int o = 16; o; o >>= 1) v += __shfl_xor_sync(0xffffffffu, v, o);
        if (lane == 0) red[0] = v;
    }
    __syncthreads();
    return red[0];
}

// -------- kernels --------
// h1 = x @ W1 (2048x2048 @ 2048x32); 32-way k-split, atomic accumulate.
// blockIdx.y==0 slice also counts degrees; block (0,0) publishes dtype flag.
__global__ void __launch_bounds__(256) k_gemm1(const float* __restrict__ X,
                                               const float* __restrict__ W,
                                               const void* __restrict__ ei) {
    __shared__ float Xs[64][64];
    __shared__ float Ws[64][H1];
    int t = threadIdx.x;
    if (blockIdx.y == 0) {
        int is64 = detect64(ei);
        if (blockIdx.x == 0 && t == 0) d_ei64 = is64;
        for (int e = blockIdx.x * 256 + t; e < NE; e += 32 * 256) {
            int d = load_ei(ei, NE + e, is64);
            if ((unsigned)d < NND) atomicAdd(&d_degc[d], 1);
        }
    }
    int row0 = blockIdx.x * 64;
    int k0 = blockIdx.y * 64;
    int tx = t & 31;
    int ty = t >> 5;
    float acc[8] = {0,0,0,0,0,0,0,0};
    #pragma unroll
    for (int i = 0; i < 4; i++) {
        int idx = t + i * 256;
        int r = idx >> 4, c = idx & 15;
        float4 v = __ldg((const float4*)&X[(size_t)(row0 + r)*NND + k0 + c*4]);
        Xs[r][4*c + 0] = v.x; Xs[r][4*c + 1] = v.y;
        Xs[r][4*c + 2] = v.z; Xs[r][4*c + 3] = v.w;
    }
    #pragma unroll
    for (int i = 0; i < 2; i++) {
        int idx = t + i * 256;
        int r = idx >> 3, c = idx & 7;
        float4 v = __ldg((const float4*)&W[(size_t)(k0 + r)*H1 + 4*c]);
        Ws[r][4*c + 0] = v.x; Ws[r][4*c + 1] = v.y;
        Ws[r][4*c + 2] = v.z; Ws[r][4*c + 3] = v.w;
    }
    __syncthreads();
    #pragma unroll 8
    for (int kk = 0; kk < 64; kk++) {
        float wv = Ws[kk][tx];
        #pragma unroll
        for (int r = 0; r < 8; r++) acc[r] = fmaf(Xs[ty + r*8][kk], wv, acc[r]);
    }
    #pragma unroll
    for (int r = 0; r < 8; r++)
        atomicAdd(&d_h1[(size_t)(row0 + ty + r*8)*H1 + tx], acc[r]);
}

// edge aggregation layer 1: one warp per edge, lane = feature
__global__ void __launch_bounds__(256) k_agg1(const void* __restrict__ ei) {
    int w = (blockIdx.x * blockDim.x + threadIdx.x) >> 5;
    int lane = threadIdx.x & 31;
    if (w >= NE) return;
    int is64 = d_ei64;
    int s = load_ei(ei, w, is64);
    int d = load_ei(ei, NE + w, is64);
    if ((unsigned)s >= NND || (unsigned)d >= NND) return;
    float norm = rsqrtf((float)(d_degc[s] + 1)) * rsqrtf((float)(d_degc[d] + 1));
    atomicAdd(&d_agg1[d*H1 + lane], d_h1[s*H1 + lane] * norm);
}

// h2 = relu(agg1 + self + b1) @ W2; one warp per node, shuffle-broadcast o1.
__global__ void __launch_bounds__(256) k_gemm2(const float* __restrict__ W2,
                                               const float* __restrict__ b1) {
    __shared__ float W2s[H1][H2];
    int t = threadIdx.x;
    for (int i = t; i < H1*H2; i += 256) W2s[i / H2][i % H2] = W2[i];
    __syncthreads();
    int w = t >> 5, lane = t & 31;
    int n = blockIdx.x * 8 + w;
    float inv = 1.f / (float)(d_degc[n] + 1);
    float o1v = fmaxf(d_agg1[n*H1 + lane] + d_h1[n*H1 + lane] * inv + __ldg(&b1[lane]), 0.f);
    float s = 0.f;
    #pragma unroll
    for (int k = 0; k < H1; k++) {
        float ok = __shfl_sync(0xffffffffu, o1v, k);
        if (lane < H2) s = fmaf(ok, W2s[k][lane], s);
    }
    if (lane < H2) d_h2[n*H2 + lane] = s;
}

// edge aggregation layer 2: thread-per-(edge,feature); last block runs colmean.
__global__ void __launch_bounds__(640) k_agg2(const void* __restrict__ ei,
                                              const float* __restrict__ b2) {
    __shared__ bool isLast;
    int t = threadIdx.x;
    int idx = blockIdx.x * 640 + t;
    int e = idx / H2, j = idx - H2 * e;
    int is64 = d_ei64;
    if (e < NE) {
        int s = load_ei(ei, e, is64);
        int d = load_ei(ei, NE + e, is64);
        if ((unsigned)s < NND && (unsigned)d < NND) {
            float norm = rsqrtf((float)(d_degc[s] + 1)) * rsqrtf((float)(d_degc[d] + 1));
            atomicAdd(&d_agg2[d*H2 + j], d_h2[s*H2 + j] * norm);
        }
    }
    __syncthreads();                       // all block atomics performed
    if (t == 0) {
        __threadfence();                   // single-thread release
        isLast = (atomicAdd(d_tick, 1u) == (unsigned)(gridDim.x - 1));
    }
    __syncthreads();
    if (!isLast) return;
    // colmean in the last block: warp wj sums column wj of relu(agg2 + self + b2)
    int wj = t >> 5, lane = t & 31;        // 20 warps, one per column
    if (wj < H2) {
        float bj = __ldg(&b2[wj]);
        float s = 0.f;
        for (int n = lane; n < NND; n += 32) {
            float inv = 1.f / (float)(d_degc[n] + 1);
            s += fmaxf(d_agg2[n*H2 + wj] + d_h2[n*H2 + wj] * inv + bj, 0.f);
        }
        #pragma unroll
        for (int o = 16; o; o >>= 1) s += __shfl_xor_sync(0xffffffffu, s, o);
        if (lane == 0) d_xactor[wj] = s * (1.f / NND);
    }
}

// Fused: logits row -> softmax stats -> per-row argmax (no probs store)
__global__ void __launch_bounds__(512) k_logits(const float* __restrict__ aW,
                                                const float* __restrict__ ab) {
    __shared__ float xa[H2];
    __shared__ float red[32];
    __shared__ float    sval[16];
    __shared__ unsigned sidx[16];
    int t = threadIdx.x;
    int row = blockIdx.x;
    if (t < H2) xa[t] = d_xactor[t];
    __syncthreads();
    size_t base = (size_t)row * NND;
    float l[4];
    {
        float4 a0 = __ldcs((const float4*)&ab[base + 4*t]);
        l[0]=a0.x; l[1]=a0.y; l[2]=a0.z; l[3]=a0.w;
    }
    #pragma unroll
    for (int k = 0; k < H2; k++) {
        float xv = xa[k];
        float4 v0 = __ldcs((const float4*)&aW[(size_t)k * NNSQ + base + 4*t]);
        l[0] = fmaf(xv, v0.x, l[0]); l[1] = fmaf(xv, v0.y, l[1]);
        l[2] = fmaf(xv, v0.z, l[2]); l[3] = fmaf(xv, v0.w, l[3]);
    }
    float m = fmaxf(fmaxf(l[0], l[1]), fmaxf(l[2], l[3]));
    m = block_reduce_max(m, red);
    float e[4]; float s = 0.f;
    #pragma unroll
    for (int c = 0; c < 4; c++) { e[c] = expf(l[c] - m); s += e[c]; }
    s = block_reduce_sum(s, red);
    float p[4];
    #pragma unroll
    for (int c = 0; c < 4; c++) p[c] = e[c] / s;
    float bv = p[0]; unsigned bc = (unsigned)(4*t);
    #pragma unroll
    for (int c = 1; c < 4; c++)
        if (p[c] > bv) { bv = p[c]; bc = (unsigned)(4*t + c); }
    unsigned gi = (unsigned)base + bc;
    warp_pair_reduce(bv, gi);
    int lane = t & 31, wid = t >> 5;
    if (lane == 0) { sval[wid] = bv; sidx[wid] = gi; }
    __syncthreads();
    if (t == 0) {
        float v = sval[0]; unsigned i = sidx[0];
        #pragma unroll
        for (int w = 1; w < 16; w++) pair_take(v, i, sval[w], sidx[w]);
        d_rowval[row] = v; d_rowidx[row] = i;
        d_rowm[row] = m; d_rowz[row] = s;
    }
}

// Single-block tail: global argmax -> prefix argmax (recompute row r1) -> output
__global__ void __launch_bounds__(256) k_tail(const float* __restrict__ aW,
                                              const float* __restrict__ ab,
                                              const float* __restrict__ cW,
                                              const float* __restrict__ cb,
                                              float* __restrict__ out, int out_size) {
    __shared__ float    sval[8];
    __shared__ unsigned sidx[8];
    __shared__ float xa[H2];
    int t = threadIdx.x;
    if (t < H2) xa[t] = d_xactor[t];
    __syncthreads();

    float v = -1.f; unsigned i = 0xFFFFFFFFu;
    for (int r = t; r < NND; r += 256) pair_take(v, i, d_rowval[r], d_rowidx[r]);
    block_pair_reduce(v, i, sval, sidx);
    unsigned idx1 = i;
    unsigned r1 = idx1 >> 11, c1 = idx1 & 2047u;

    float v2 = -1.f; unsigned i2 = 0xFFFFFFFFu;
    for (unsigned r = t; r < r1; r += 256) pair_take(v2, i2, d_rowval[r], d_rowidx[r]);
    if (c1 > 0) {
        float m1 = d_rowm[r1], z1 = d_rowz[r1];
        size_t base = (size_t)r1 * NND;
        for (unsigned c = t; c < c1; c += 256) {
            float l = __ldg(&ab[base + c]);
            #pragma unroll
            for (int k = 0; k < H2; k++)
                l = fmaf(xa[k], __ldg(&aW[(size_t)k * NNSQ + base + c]), l);
            float p = expf(l - m1) / z1;
            pair_take(v2, i2, p, (unsigned)base + c);
        }
    }
    block_pair_reduce(v2, i2, sval, sidx);
    unsigned idx2 = (v2 >= 0.f) ? i2 : 0u;

    if (t == 0) {
        unsigned a0 = idx1 >> 11, a1 = idx1 & 2047u;
        unsigned a2 = idx2 >> 11, a3 = idx2 & 2047u;
        float m0 = d_rowm[0], z0 = d_rowz[0];
        unsigned ai[4] = {a0, a1, a2, a3};
        float lp[4];
        #pragma unroll
        for (int q = 0; q < 4; q++) {
            unsigned j = ai[q];
            float l = ab[j];
            #pragma unroll
            for (int k = 0; k < H2; k++)
                l = fmaf(xa[k], aW[(size_t)k * NNSQ + j], l);
            float p = expf(l - m0) / z0;
            lp[q] = -logf(p);
        }
        float critic = cb[0];
        #pragma unroll
        for (int k = 0; k < H2; k++) critic = fmaf(xa[k], cW[k], critic);
        float o[9];
        o[0] = (float)a0; o[1] = (float)a1; o[2] = (float)a2; o[3] = (float)a3;
        o[4] = lp[0]; o[5] = lp[1]; o[6] = lp[2]; o[7] = lp[3];
        o[8] = critic;
        int n = out_size < 9 ? out_size : 9;
        for (int q = 0; q < n; q++) out[q] = o[q];
    }
}

extern "C" void kernel_launch(void* const* d_in, const int* in_sizes, int n_in,
                              void* d_out, int out_size) {
    const float* x   = (const float*)d_in[0];
    const void*  ei  = d_in[1];
    const float* W1  = (const float*)d_in[2];
    const float* b1  = (const float*)d_in[3];
    const float* W2  = (const float*)d_in[4];
    const float* b2  = (const float*)d_in[5];
    const float* aW  = (const float*)d_in[6];
    const float* ab  = (const float*)d_in[7];
    const float* cW  = (const float*)d_in[8];
    const float* cb  = (const float*)d_in[9];
    float* out = (float*)d_out;

    void* scratch_ptr = nullptr;
    cudaGetSymbolAddress(&scratch_ptr, d_scratch);
    cudaMemsetAsync(scratch_ptr, 0, SC_TOTAL * sizeof(float), 0);

    k_gemm1  <<<dim3(32, 32), 256>>>(x, W1, ei);
    k_agg1   <<<8192,256>>>(ei);
    k_gemm2  <<<256, 256>>>(W2, b1);
    k_agg2   <<<2048,640>>>(ei, b2);
    k_logits <<<2048,512>>>(aW, ab);
    k_tail   <<<1,   256>>>(aW, ab, cW, cb, out, out_size);
}

// round 14
// speedup vs baseline: 1.2460x; 1.2262x over previous
#include <cuda_runtime.h>
#include <stdint.h>
#include <math.h>

#define NND 2048
#define NE  65536
#define H1  32
#define H2  20
#define NNSQ (NND*NND)

// -------- zeroed scratch (single cudaMemsetAsync per call) --------
#define SC_DEGC  0                       // int counts [NND]
#define SC_H1    (SC_DEGC + NND)
#define SC_AGG1  (SC_H1 + NND*H1)
#define SC_AGG2  (SC_AGG1 + NND*H1)
#define SC_TOTAL (SC_AGG2 + NND*H2)
__device__ __align__(16) float d_scratch[SC_TOTAL];
#define d_degc  ((int*)(d_scratch + SC_DEGC))
#define d_h1    (d_scratch + SC_H1)
#define d_agg1  (d_scratch + SC_AGG1)
#define d_agg2  (d_scratch + SC_AGG2)

__device__ __align__(16) float d_h2[NND*H2];
__device__ float d_xactor[H2];
__device__ float    d_rowval[NND];
__device__ unsigned d_rowidx[NND];
__device__ float    d_rowm[NND];
__device__ float    d_rowz[NND];
__device__ int      d_ei64;   // published by k_gemm1 block (0,0)

// dual-dtype edge index accessor (pos in [0, 2*NE))
__device__ __forceinline__ int load_ei(const void* ei, int pos, int is64) {
    if (is64) return (int)((const long long*)ei)[pos];
    return ((const int*)ei)[pos];
}

__device__ __forceinline__ int detect64(const void* ei) {
    const long long* p = (const long long*)ei;
    int is64 = 1;
    #pragma unroll
    for (int k = 0; k < 16; k++) {
        long long v = p[k];
        if (v < 0 || v >= NND) is64 = 0;
    }
    return is64;
}

// pair combine: max value, tie -> smaller index (first occurrence)
__device__ __forceinline__ void pair_take(float& v, unsigned& i, float v2, unsigned i2) {
    if (v2 > v || (v2 == v && i2 < i)) { v = v2; i = i2; }
}

__device__ __forceinline__ void warp_pair_reduce(float& v, unsigned& i) {
    #pragma unroll
    for (int o = 16; o; o >>= 1) {
        float    v2 = __shfl_xor_sync(0xffffffffu, v, o);
        unsigned i2 = __shfl_xor_sync(0xffffffffu, i, o);
        pair_take(v, i, v2, i2);
    }
}

__device__ __forceinline__ void block_pair_reduce(float& v, unsigned& i,
                                                  float* sval, unsigned* sidx) {
    warp_pair_reduce(v, i);
    int lane = threadIdx.x & 31, wid = threadIdx.x >> 5;
    if (lane == 0) { sval[wid] = v; sidx[wid] = i; }
    __syncthreads();
    if (wid == 0) {
        int nw = (blockDim.x + 31) >> 5;
        if (lane < nw) { v = sval[lane]; i = sidx[lane]; }
        else           { v = -3.402823e38f; i = 0xFFFFFFFFu; }
        warp_pair_reduce(v, i);
        if (lane == 0) { sval[0] = v; sidx[0] = i; }
    }
    __syncthreads();
    v = sval[0]; i = sidx[0];
    __syncthreads();
}

__device__ __forceinline__ float block_reduce_max(float v, float* red) {
    __syncthreads();
    int lane = threadIdx.x & 31, wid = threadIdx.x >> 5;
    #pragma unroll
    for (int o = 16; o; o >>= 1) v = fmaxf(v, __shfl_xor_sync(0xffffffffu, v, o));
    if (lane == 0) red[wid] = v;
    __syncthreads();
    if (wid == 0) {
        int nw = (blockDim.x + 31) >> 5;
        v = (lane < nw) ? red[lane] : -3.402823e38f;
        #pragma unroll
        for (int o = 16; o; o >>= 1) v = fmaxf(v, __shfl_xor_sync(0xffffffffu, v, o));
        if (lane == 0) red[0] = v;
    }
    __syncthreads();
    return red[0];
}

__device__ __forceinline__ float block_reduce_sum(float v, float* red) {
    __syncthreads();
    int lane = threadIdx.x & 31, wid = threadIdx.x >> 5;
    #pragma unroll
    for (int o = 16; o; o >>= 1) v += __shfl_xor_sync(0xffffffffu, v, o);
    if (lane == 0) red[wid] = v;
    __syncthreads();
    if (wid == 0) {
        int nw = (blockDim.x + 31) >> 5;
        v = (lane < nw) ? red[lane] : 0.f;
        #pragma unroll
        for (int o = 16; o; o >>= 1) v += __shfl_xor_sync(0xffffffffu, v, o);
        if (lane == 0) red[0] = v;
    }
    __syncthreads();
    return red[0];
}

// -------- kernels --------
// h1 = x @ W1 (2048x2048 @ 2048x32); 32-way k-split, atomic accumulate.
// blockIdx.y==0 slice also counts degrees; block (0,0) publishes dtype flag.
__global__ void __launch_bounds__(256) k_gemm1(const float* __restrict__ X,
                                               const float* __restrict__ W,
                                               const void* __restrict__ ei) {
    __shared__ float Xs[64][64];
    __shared__ float Ws[64][H1];
    int t = threadIdx.x;
    if (blockIdx.y == 0) {
        int is64 = detect64(ei);
        if (blockIdx.x == 0 && t == 0) d_ei64 = is64;
        for (int e = blockIdx.x * 256 + t; e < NE; e += 32 * 256) {
            int d = load_ei(ei, NE + e, is64);
            if ((unsigned)d < NND) atomicAdd(&d_degc[d], 1);
        }
    }
    int row0 = blockIdx.x * 64;
    int k0 = blockIdx.y * 64;
    int tx = t & 31;
    int ty = t >> 5;
    float acc[8] = {0,0,0,0,0,0,0,0};
    #pragma unroll
    for (int i = 0; i < 4; i++) {
        int idx = t + i * 256;
        int r = idx >> 4, c = idx & 15;
        float4 v = __ldg((const float4*)&X[(size_t)(row0 + r)*NND + k0 + c*4]);
        Xs[r][4*c + 0] = v.x; Xs[r][4*c + 1] = v.y;
        Xs[r][4*c + 2] = v.z; Xs[r][4*c + 3] = v.w;
    }
    #pragma unroll
    for (int i = 0; i < 2; i++) {
        int idx = t + i * 256;
        int r = idx >> 3, c = idx & 7;
        float4 v = __ldg((const float4*)&W[(size_t)(k0 + r)*H1 + 4*c]);
        Ws[r][4*c + 0] = v.x; Ws[r][4*c + 1] = v.y;
        Ws[r][4*c + 2] = v.z; Ws[r][4*c + 3] = v.w;
    }
    __syncthreads();
    #pragma unroll 8
    for (int kk = 0; kk < 64; kk++) {
        float wv = Ws[kk][tx];
        #pragma unroll
        for (int r = 0; r < 8; r++) acc[r] = fmaf(Xs[ty + r*8][kk], wv, acc[r]);
    }
    #pragma unroll
    for (int r = 0; r < 8; r++)
        atomicAdd(&d_h1[(size_t)(row0 + ty + r*8)*H1 + tx], acc[r]);
}

// edge aggregation layer 1: one warp per edge, lane = feature
__global__ void __launch_bounds__(256) k_agg1(const void* __restrict__ ei) {
    int w = (blockIdx.x * blockDim.x + threadIdx.x) >> 5;
    int lane = threadIdx.x & 31;
    if (w >= NE) return;
    int is64 = d_ei64;
    int s = load_ei(ei, w, is64);
    int d = load_ei(ei, NE + w, is64);
    if ((unsigned)s >= NND || (unsigned)d >= NND) return;
    float norm = rsqrtf((float)(d_degc[s] + 1)) * rsqrtf((float)(d_degc[d] + 1));
    atomicAdd(&d_agg1[d*H1 + lane], d_h1[s*H1 + lane] * norm);
}

// h2 = relu(agg1 + self + b1) @ W2; one warp per node, shuffle-broadcast o1.
__global__ void __launch_bounds__(256) k_gemm2(const float* __restrict__ W2,
                                               const float* __restrict__ b1) {
    __shared__ float W2s[H1][H2];
    int t = threadIdx.x;
    for (int i = t; i < H1*H2; i += 256) W2s[i / H2][i % H2] = W2[i];
    __syncthreads();
    int w = t >> 5, lane = t & 31;
    int n = blockIdx.x * 8 + w;
    float inv = 1.f / (float)(d_degc[n] + 1);
    float o1v = fmaxf(d_agg1[n*H1 + lane] + d_h1[n*H1 + lane] * inv + __ldg(&b1[lane]), 0.f);
    float s = 0.f;
    #pragma unroll
    for (int k = 0; k < H1; k++) {
        float ok = __shfl_sync(0xffffffffu, o1v, k);
        if (lane < H2) s = fmaf(ok, W2s[k][lane], s);
    }
    if (lane < H2) d_h2[n*H2 + lane] = s;
}

// edge aggregation layer 2: thread-per-(edge,feature); 640 = 32 edges x 20 features
__global__ void __launch_bounds__(640) k_agg2(const void* __restrict__ ei) {
    int idx = blockIdx.x * 640 + threadIdx.x;
    int e = idx / H2, j = idx - H2 * e;
    if (e >= NE) return;
    int is64 = d_ei64;
    int s = load_ei(ei, e, is64);
    int d = load_ei(ei, NE + e, is64);
    if ((unsigned)s >= NND || (unsigned)d >= NND) return;
    float norm = rsqrtf((float)(d_degc[s] + 1)) * rsqrtf((float)(d_degc[d] + 1));
    atomicAdd(&d_agg2[d*H2 + j], d_h2[s*H2 + j] * norm);
}

// x_actor[j] = mean over nodes of relu(agg2 + self + b2)[:, j]   (relu2 fused)
__global__ void k_colmean(const float* __restrict__ b2) {
    __shared__ float red[32];
    int j = blockIdx.x;
    float bj = b2[j];
    float s = 0.f;
    for (int n = threadIdx.x; n < NND; n += blockDim.x) {
        float inv = 1.f / (float)(d_degc[n] + 1);
        float o2 = fmaxf(d_agg2[n*H2 + j] + d_h2[n*H2 + j] * inv + bj, 0.f);
        s += o2;
    }
    s = block_reduce_sum(s, red);
    if (threadIdx.x == 0) d_xactor[j] = s * (1.f / NND);
}

// Fused: logits row -> softmax stats -> per-row argmax (no probs store)
// 512 threads; each thread owns 4 consecutive cols (one float4 per aW row).
__global__ void __launch_bounds__(512) k_logits(const float* __restrict__ aW,
                                                const float* __restrict__ ab) {
    __shared__ float xa[H2];
    __shared__ float red[32];
    __shared__ float    sval[16];
    __shared__ unsigned sidx[16];
    int t = threadIdx.x;
    int row = blockIdx.x;
    if (t < H2) xa[t] = d_xactor[t];
    __syncthreads();
    size_t base = (size_t)row * NND;
    float l[4];
    {
        float4 a0 = __ldcs((const float4*)&ab[base + 4*t]);
        l[0]=a0.x; l[1]=a0.y; l[2]=a0.z; l[3]=a0.w;
    }
    #pragma unroll
    for (int k = 0; k < H2; k++) {
        float xv = xa[k];
        float4 v0 = __ldcs((const float4*)&aW[(size_t)k * NNSQ + base + 4*t]);
        l[0] = fmaf(xv, v0.x, l[0]); l[1] = fmaf(xv, v0.y, l[1]);
        l[2] = fmaf(xv, v0.z, l[2]); l[3] = fmaf(xv, v0.w, l[3]);
    }
    float m = fmaxf(fmaxf(l[0], l[1]), fmaxf(l[2], l[3]));
    m = block_reduce_max(m, red);
    float e[4]; float s = 0.f;
    #pragma unroll
    for (int c = 0; c < 4; c++) { e[c] = expf(l[c] - m); s += e[c]; }
    s = block_reduce_sum(s, red);
    float p[4];
    #pragma unroll
    for (int c = 0; c < 4; c++) p[c] = e[c] / s;
    float bv = p[0]; unsigned bc = (unsigned)(4*t);
    #pragma unroll
    for (int c = 1; c < 4; c++)
        if (p[c] > bv) { bv = p[c]; bc = (unsigned)(4*t + c); }
    unsigned gi = (unsigned)base + bc;
    warp_pair_reduce(bv, gi);
    int lane = t & 31, wid = t >> 5;
    if (lane == 0) { sval[wid] = bv; sidx[wid] = gi; }
    __syncthreads();
    if (t == 0) {
        float v = sval[0]; unsigned i = sidx[0];
        #pragma unroll
        for (int w = 1; w < 16; w++) pair_take(v, i, sval[w], sidx[w]);
        d_rowval[row] = v; d_rowidx[row] = i;
        d_rowm[row] = m; d_rowz[row] = s;
    }
}

// Single-block tail: global argmax -> prefix argmax (recompute row r1) -> output
__global__ void __launch_bounds__(256) k_tail(const float* __restrict__ aW,
                                              const float* __restrict__ ab,
                                              const float* __restrict__ cW,
                                              const float* __restrict__ cb,
                                              float* __restrict__ out, int out_size) {
    __shared__ float    sval[8];
    __shared__ unsigned sidx[8];
    __shared__ float xa[H2];
    int t = threadIdx.x;
    if (t < H2) xa[t] = d_xactor[t];
    __syncthreads();

    float v = -1.f; unsigned i = 0xFFFFFFFFu;
    for (int r = t; r < NND; r += 256) pair_take(v, i, d_rowval[r], d_rowidx[r]);
    block_pair_reduce(v, i, sval, sidx);
    unsigned idx1 = i;
    unsigned r1 = idx1 >> 11, c1 = idx1 & 2047u;

    float v2 = -1.f; unsigned i2 = 0xFFFFFFFFu;
    for (unsigned r = t; r < r1; r += 256) pair_take(v2, i2, d_rowval[r], d_rowidx[r]);
    if (c1 > 0) {
        float m1 = d_rowm[r1], z1 = d_rowz[r1];
        size_t base = (size_t)r1 * NND;
        for (unsigned c = t; c < c1; c += 256) {
            float l = __ldg(&ab[base + c]);
            #pragma unroll
            for (int k = 0; k < H2; k++)
                l = fmaf(xa[k], __ldg(&aW[(size_t)k * NNSQ + base + c]), l);
            float p = expf(l - m1) / z1;
            pair_take(v2, i2, p, (unsigned)base + c);
        }
    }
    block_pair_reduce(v2, i2, sval, sidx);
    unsigned idx2 = (v2 >= 0.f) ? i2 : 0u;

    if (t == 0) {
        unsigned a0 = idx1 >> 11, a1 = idx1 & 2047u;
        unsigned a2 = idx2 >> 11, a3 = idx2 & 2047u;
        float m0 = d_rowm[0], z0 = d_rowz[0];
        unsigned ai[4] = {a0, a1, a2, a3};
        float lp[4];
        #pragma unroll
        for (int q = 0; q < 4; q++) {
            unsigned j = ai[q];
            float l = ab[j];
            #pragma unroll
            for (int k = 0; k < H2; k++)
                l = fmaf(xa[k], aW[(size_t)k * NNSQ + j], l);
            float p = expf(l - m0) / z0;
            lp[q] = -logf(p);
        }
        float critic = cb[0];
        #pragma unroll
        for (int k = 0; k < H2; k++) critic = fmaf(xa[k], cW[k], critic);
        float o[9];
        o[0] = (float)a0; o[1] = (float)a1; o[2] = (float)a2; o[3] = (float)a3;
        o[4] = lp[0]; o[5] = lp[1]; o[6] = lp[2]; o[7] = lp[3];
        o[8] = critic;
        int n = out_size < 9 ? out_size : 9;
        for (int q = 0; q < n; q++) out[q] = o[q];
    }
}

extern "C" void kernel_launch(void* const* d_in, const int* in_sizes, int n_in,
                              void* d_out, int out_size) {
    const float* x   = (const float*)d_in[0];
    const void*  ei  = d_in[1];
    const float* W1  = (const float*)d_in[2];
    const float* b1  = (const float*)d_in[3];
    const float* W2  = (const float*)d_in[4];
    const float* b2  = (const float*)d_in[5];
    const float* aW  = (const float*)d_in[6];
    const float* ab  = (const float*)d_in[7];
    const float* cW  = (const float*)d_in[8];
    const float* cb  = (const float*)d_in[9];
    float* out = (float*)d_out;

    void* scratch_ptr = nullptr;
    cudaGetSymbolAddress(&scratch_ptr, d_scratch);
    cudaMemsetAsync(scratch_ptr, 0, SC_TOTAL * sizeof(float), 0);

    k_gemm1  <<<dim3(32, 32), 256>>>(x, W1, ei);
    k_agg1   <<<8192,256>>>(ei);
    k_gemm2  <<<256, 256>>>(W2, b1);
    k_agg2   <<<2048,640>>>(ei);
    k_colmean<<<20,  256>>>(b2);
    k_logits <<<2048,512>>>(aW, ab);
    k_tail   <<<1,   256>>>(aW, ab, cW, cb, out, out_size);
}

// round 15
// speedup vs baseline: 1.2920x; 1.0369x over previous
#include <cuda_runtime.h>
#include <stdint.h>
#include <math.h>

#define NND 2048
#define NE  65536
#define H1  32
#define H2  20
#define NNSQ (NND*NND)

// -------- zeroed scratch (single cudaMemsetAsync per call) --------
#define SC_DEGC  0                       // int counts [NND]
#define SC_H1    (SC_DEGC + NND)
#define SC_AGG1  (SC_H1 + NND*H1)
#define SC_AGG2  (SC_AGG1 + NND*H1)
#define SC_TOTAL (SC_AGG2 + NND*H2)
__device__ __align__(16) float d_scratch[SC_TOTAL];
#define d_degc  ((int*)(d_scratch + SC_DEGC))
#define d_h1    (d_scratch + SC_H1)
#define d_agg1  (d_scratch + SC_AGG1)
#define d_agg2  (d_scratch + SC_AGG2)

__device__ __align__(16) float d_h2[NND*H2];
__device__ float d_xactor[H2];
__device__ float    d_rowval[NND];
__device__ unsigned d_rowidx[NND];
__device__ float    d_rowm[NND];
__device__ float    d_rowz[NND];
__device__ int      d_ei64;   // published by k_gemm1 block (0,0)

// dual-dtype edge index accessor (pos in [0, 2*NE))
__device__ __forceinline__ int load_ei(const void* ei, int pos, int is64) {
    if (is64) return (int)((const long long*)ei)[pos];
    return ((const int*)ei)[pos];
}

__device__ __forceinline__ int detect64(const void* ei) {
    const long long* p = (const long long*)ei;
    int is64 = 1;
    #pragma unroll
    for (int k = 0; k < 16; k++) {
        long long v = p[k];
        if (v < 0 || v >= NND) is64 = 0;
    }
    return is64;
}

// 16B vector reduction (sm_90+): 1 transaction for 4 floats
__device__ __forceinline__ void red_add_v4(float* dst, float4 v) {
    asm volatile("red.global.add.v4.f32 [%0], {%1, %2, %3, %4};"
                 :: "l"(dst), "f"(v.x), "f"(v.y), "f"(v.z), "f"(v.w)
                 : "memory");
}

// pair combine: max value, tie -> smaller index (first occurrence)
__device__ __forceinline__ void pair_take(float& v, unsigned& i, float v2, unsigned i2) {
    if (v2 > v || (v2 == v && i2 < i)) { v = v2; i = i2; }
}

__device__ __forceinline__ void warp_pair_reduce(float& v, unsigned& i) {
    #pragma unroll
    for (int o = 16; o; o >>= 1) {
        float    v2 = __shfl_xor_sync(0xffffffffu, v, o);
        unsigned i2 = __shfl_xor_sync(0xffffffffu, i, o);
        pair_take(v, i, v2, i2);
    }
}

__device__ __forceinline__ void block_pair_reduce(float& v, unsigned& i,
                                                  float* sval, unsigned* sidx) {
    warp_pair_reduce(v, i);
    int lane = threadIdx.x & 31, wid = threadIdx.x >> 5;
    if (lane == 0) { sval[wid] = v; sidx[wid] = i; }
    __syncthreads();
    if (wid == 0) {
        int nw = (blockDim.x + 31) >> 5;
        if (lane < nw) { v = sval[lane]; i = sidx[lane]; }
        else           { v = -3.402823e38f; i = 0xFFFFFFFFu; }
        warp_pair_reduce(v, i);
        if (lane == 0) { sval[0] = v; sidx[0] = i; }
    }
    __syncthreads();
    v = sval[0]; i = sidx[0];
    __syncthreads();
}

__device__ __forceinline__ float block_reduce_max(float v, float* red) {
    __syncthreads();
    int lane = threadIdx.x & 31, wid = threadIdx.x >> 5;
    #pragma unroll
    for (int o = 16; o; o >>= 1) v = fmaxf(v, __shfl_xor_sync(0xffffffffu, v, o));
    if (lane == 0) red[wid] = v;
    __syncthreads();
    if (wid == 0) {
        int nw = (blockDim.x + 31) >> 5;
        v = (lane < nw) ? red[lane] : -3.402823e38f;
        #pragma unroll
        for (int o = 16; o; o >>= 1) v = fmaxf(v, __shfl_xor_sync(0xffffffffu, v, o));
        if (lane == 0) red[0] = v;
    }
    __syncthreads();
    return red[0];
}

__device__ __forceinline__ float block_reduce_sum(float v, float* red) {
    __syncthreads();
    int lane = threadIdx.x & 31, wid = threadIdx.x >> 5;
    #pragma unroll
    for (int o = 16; o; o >>= 1) v += __shfl_xor_sync(0xffffffffu, v, o);
    if (lane == 0) red[wid] = v;
    __syncthreads();
    if (wid == 0) {
        int nw = (blockDim.x + 31) >> 5;
        v = (lane < nw) ? red[lane] : 0.f;
        #pragma unroll
        for (int o = 16; o; o >>= 1) v += __shfl_xor_sync(0xffffffffu, v, o);
        if (lane == 0) red[0] = v;
    }
    __syncthreads();
    return red[0];
}

// -------- kernels --------
// h1 = x @ W1 (2048x2048 @ 2048x32); 32-way k-split, atomic accumulate.
// blockIdx.y==0 slice also counts degrees; block (0,0) publishes dtype flag.
__global__ void __launch_bounds__(256) k_gemm1(const float* __restrict__ X,
                                               const float* __restrict__ W,
                                               const void* __restrict__ ei) {
    __shared__ float Xs[64][64];
    __shared__ float Ws[64][H1];
    int t = threadIdx.x;
    if (blockIdx.y == 0) {
        int is64 = detect64(ei);
        if (blockIdx.x == 0 && t == 0) d_ei64 = is64;
        for (int e = blockIdx.x * 256 + t; e < NE; e += 32 * 256) {
            int d = load_ei(ei, NE + e, is64);
            if ((unsigned)d < NND) atomicAdd(&d_degc[d], 1);
        }
    }
    int row0 = blockIdx.x * 64;
    int k0 = blockIdx.y * 64;
    int tx = t & 31;
    int ty = t >> 5;
    float acc[8] = {0,0,0,0,0,0,0,0};
    #pragma unroll
    for (int i = 0; i < 4; i++) {
        int idx = t + i * 256;
        int r = idx >> 4, c = idx & 15;
        float4 v = __ldg((const float4*)&X[(size_t)(row0 + r)*NND + k0 + c*4]);
        Xs[r][4*c + 0] = v.x; Xs[r][4*c + 1] = v.y;
        Xs[r][4*c + 2] = v.z; Xs[r][4*c + 3] = v.w;
    }
    #pragma unroll
    for (int i = 0; i < 2; i++) {
        int idx = t + i * 256;
        int r = idx >> 3, c = idx & 7;
        float4 v = __ldg((const float4*)&W[(size_t)(k0 + r)*H1 + 4*c]);
        Ws[r][4*c + 0] = v.x; Ws[r][4*c + 1] = v.y;
        Ws[r][4*c + 2] = v.z; Ws[r][4*c + 3] = v.w;
    }
    __syncthreads();
    #pragma unroll 8
    for (int kk = 0; kk < 64; kk++) {
        float wv = Ws[kk][tx];
        #pragma unroll
        for (int r = 0; r < 8; r++) acc[r] = fmaf(Xs[ty + r*8][kk], wv, acc[r]);
    }
    #pragma unroll
    for (int r = 0; r < 8; r++)
        atomicAdd(&d_h1[(size_t)(row0 + ty + r*8)*H1 + tx], acc[r]);
}

// edge aggregation layer 1: warp = 4 edges x 8 lanes; one v4 red per lane.
__global__ void __launch_bounds__(256) k_agg1(const void* __restrict__ ei) {
    int w = (blockIdx.x * 256 + threadIdx.x) >> 5;   // warp id
    int lane = threadIdx.x & 31;
    int el = lane >> 3;                               // edge within warp 0..3
    int sub = lane & 7;                               // float4 group 0..7
    int e = w * 4 + el;
    if (e >= NE) return;
    int is64 = d_ei64;
    int s = load_ei(ei, e, is64);
    int d = load_ei(ei, NE + e, is64);
    if ((unsigned)s >= NND || (unsigned)d >= NND) return;
    float norm = rsqrtf((float)(d_degc[s] + 1)) * rsqrtf((float)(d_degc[d] + 1));
    float4 h = *(const float4*)&d_h1[s*H1 + sub*4];
    red_add_v4(&d_agg1[d*H1 + sub*4],
               make_float4(h.x*norm, h.y*norm, h.z*norm, h.w*norm));
}

// h2 = relu(agg1 + self + b1) @ W2; one warp per node, shuffle-broadcast o1.
__global__ void __launch_bounds__(256) k_gemm2(const float* __restrict__ W2,
                                               const float* __restrict__ b1) {
    __shared__ float W2s[H1][H2];
    int t = threadIdx.x;
    for (int i = t; i < H1*H2; i += 256) W2s[i / H2][i % H2] = W2[i];
    __syncthreads();
    int w = t >> 5, lane = t & 31;
    int n = blockIdx.x * 8 + w;
    float inv = 1.f / (float)(d_degc[n] + 1);
    float o1v = fmaxf(d_agg1[n*H1 + lane] + d_h1[n*H1 + lane] * inv + __ldg(&b1[lane]), 0.f);
    float s = 0.f;
    #pragma unroll
    for (int k = 0; k < H1; k++) {
        float ok = __shfl_sync(0xffffffffu, o1v, k);
        if (lane < H2) s = fmaf(ok, W2s[k][lane], s);
    }
    if (lane < H2) d_h2[n*H2 + lane] = s;
}

// edge aggregation layer 2: thread-per-(edge, float4-group); 5 groups x 64K edges.
// Row stride H2=20 floats = 80 bytes => every group offset is 16B-aligned.
__global__ void __launch_bounds__(640) k_agg2(const void* __restrict__ ei) {
    int idx = blockIdx.x * 640 + threadIdx.x;
    int e = idx / 5, g = idx - 5 * e;
    if (e >= NE) return;
    int is64 = d_ei64;
    int s = load_ei(ei, e, is64);
    int d = load_ei(ei, NE + e, is64);
    if ((unsigned)s >= NND || (unsigned)d >= NND) return;
    float norm = rsqrtf((float)(d_degc[s] + 1)) * rsqrtf((float)(d_degc[d] + 1));
    float4 h = *(const float4*)&d_h2[s*H2 + g*4];
    red_add_v4(&d_agg2[d*H2 + g*4],
               make_float4(h.x*norm, h.y*norm, h.z*norm, h.w*norm));
}

// x_actor[j] = mean over nodes of relu(agg2 + self + b2)[:, j]   (relu2 fused)
__global__ void k_colmean(const float* __restrict__ b2) {
    __shared__ float red[32];
    int j = blockIdx.x;
    float bj = b2[j];
    float s = 0.f;
    for (int n = threadIdx.x; n < NND; n += blockDim.x) {
        float inv = 1.f / (float)(d_degc[n] + 1);
        float o2 = fmaxf(d_agg2[n*H2 + j] + d_h2[n*H2 + j] * inv + bj, 0.f);
        s += o2;
    }
    s = block_reduce_sum(s, red);
    if (threadIdx.x == 0) d_xactor[j] = s * (1.f / NND);
}

// Fused: logits row -> softmax stats -> per-row argmax (no probs store)
// 512 threads; each thread owns 4 consecutive cols (one float4 per aW row).
__global__ void __launch_bounds__(512) k_logits(const float* __restrict__ aW,
                                                const float* __restrict__ ab) {
    __shared__ float xa[H2];
    __shared__ float red[32];
    __shared__ float    sval[16];
    __shared__ unsigned sidx[16];
    int t = threadIdx.x;
    int row = blockIdx.x;
    if (t < H2) xa[t] = d_xactor[t];
    __syncthreads();
    size_t base = (size_t)row * NND;
    float l[4];
    {
        float4 a0 = __ldcs((const float4*)&ab[base + 4*t]);
        l[0]=a0.x; l[1]=a0.y; l[2]=a0.z; l[3]=a0.w;
    }
    #pragma unroll
    for (int k = 0; k < H2; k++) {
        float xv = xa[k];
        float4 v0 = __ldcs((const float4*)&aW[(size_t)k * NNSQ + base + 4*t]);
        l[0] = fmaf(xv, v0.x, l[0]); l[1] = fmaf(xv, v0.y, l[1]);
        l[2] = fmaf(xv, v0.z, l[2]); l[3] = fmaf(xv, v0.w, l[3]);
    }
    float m = fmaxf(fmaxf(l[0], l[1]), fmaxf(l[2], l[3]));
    m = block_reduce_max(m, red);
    float e[4]; float s = 0.f;
    #pragma unroll
    for (int c = 0; c < 4; c++) { e[c] = expf(l[c] - m); s += e[c]; }
    s = block_reduce_sum(s, red);
    float p[4];
    #pragma unroll
    for (int c = 0; c < 4; c++) p[c] = e[c] / s;
    float bv = p[0]; unsigned bc = (unsigned)(4*t);
    #pragma unroll
    for (int c = 1; c < 4; c++)
        if (p[c] > bv) { bv = p[c]; bc = (unsigned)(4*t + c); }
    unsigned gi = (unsigned)base + bc;
    warp_pair_reduce(bv, gi);
    int lane = t & 31, wid = t >> 5;
    if (lane == 0) { sval[wid] = bv; sidx[wid] = gi; }
    __syncthreads();
    if (t == 0) {
        float v = sval[0]; unsigned i = sidx[0];
        #pragma unroll
        for (int w = 1; w < 16; w++) pair_take(v, i, sval[w], sidx[w]);
        d_rowval[row] = v; d_rowidx[row] = i;
        d_rowm[row] = m; d_rowz[row] = s;
    }
}

// Single-block tail: global argmax -> prefix argmax (recompute row r1) -> output
__global__ void __launch_bounds__(256) k_tail(const float* __restrict__ aW,
                                              const float* __restrict__ ab,
                                              const float* __restrict__ cW,
                                              const float* __restrict__ cb,
                                              float* __restrict__ out, int out_size) {
    __shared__ float    sval[8];
    __shared__ unsigned sidx[8];
    __shared__ float xa[H2];
    int t = threadIdx.x;
    if (t < H2) xa[t] = d_xactor[t];
    __syncthreads();

    float v = -1.f; unsigned i = 0xFFFFFFFFu;
    for (int r = t; r < NND; r += 256) pair_take(v, i, d_rowval[r], d_rowidx[r]);
    block_pair_reduce(v, i, sval, sidx);
    unsigned idx1 = i;
    unsigned r1 = idx1 >> 11, c1 = idx1 & 2047u;

    float v2 = -1.f; unsigned i2 = 0xFFFFFFFFu;
    for (unsigned r = t; r < r1; r += 256) pair_take(v2, i2, d_rowval[r], d_rowidx[r]);
    if (c1 > 0) {
        float m1 = d_rowm[r1], z1 = d_rowz[r1];
        size_t base = (size_t)r1 * NND;
        for (unsigned c = t; c < c1; c += 256) {
            float l = __ldg(&ab[base + c]);
            #pragma unroll
            for (int k = 0; k < H2; k++)
                l = fmaf(xa[k], __ldg(&aW[(size_t)k * NNSQ + base + c]), l);
            float p = expf(l - m1) / z1;
            pair_take(v2, i2, p, (unsigned)base + c);
        }
    }
    block_pair_reduce(v2, i2, sval, sidx);
    unsigned idx2 = (v2 >= 0.f) ? i2 : 0u;

    if (t == 0) {
        unsigned a0 = idx1 >> 11, a1 = idx1 & 2047u;
        unsigned a2 = idx2 >> 11, a3 = idx2 & 2047u;
        float m0 = d_rowm[0], z0 = d_rowz[0];
        unsigned ai[4] = {a0, a1, a2, a3};
        float lp[4];
        #pragma unroll
        for (int q = 0; q < 4; q++) {
            unsigned j = ai[q];
            float l = ab[j];
            #pragma unroll
            for (int k = 0; k < H2; k++)
                l = fmaf(xa[k], aW[(size_t)k * NNSQ + j], l);
            float p = expf(l - m0) / z0;
            lp[q] = -logf(p);
        }
        float critic = cb[0];
        #pragma unroll
        for (int k = 0; k < H2; k++) critic = fmaf(xa[k], cW[k], critic);
        float o[9];
        o[0] = (float)a0; o[1] = (float)a1; o[2] = (float)a2; o[3] = (float)a3;
        o[4] = lp[0]; o[5] = lp[1]; o[6] = lp[2]; o[7] = lp[3];
        o[8] = critic;
        int n = out_size < 9 ? out_size : 9;
        for (int q = 0; q < n; q++) out[q] = o[q];
    }
}

extern "C" void kernel_launch(void* const* d_in, const int* in_sizes, int n_in,
                              void* d_out, int out_size) {
    const float* x   = (const float*)d_in[0];
    const void*  ei  = d_in[1];
    const float* W1  = (const float*)d_in[2];
    const float* b1  = (const float*)d_in[3];
    const float* W2  = (const float*)d_in[4];
    const float* b2  = (const float*)d_in[5];
    const float* aW  = (const float*)d_in[6];
    const float* ab  = (const float*)d_in[7];
    const float* cW  = (const float*)d_in[8];
    const float* cb  = (const float*)d_in[9];
    float* out = (float*)d_out;

    void* scratch_ptr = nullptr;
    cudaGetSymbolAddress(&scratch_ptr, d_scratch);
    cudaMemsetAsync(scratch_ptr, 0, SC_TOTAL * sizeof(float), 0);

    k_gemm1  <<<dim3(32, 32), 256>>>(x, W1, ei);
    k_agg1   <<<2048,256>>>(ei);
    k_gemm2  <<<256, 256>>>(W2, b1);
    k_agg2   <<<512, 640>>>(ei);
    k_colmean<<<20,  256>>>(b2);
    k_logits <<<2048,512>>>(aW, ab);
    k_tail   <<<1,   256>>>(aW, ab, cW, cb, out, out_size);
}